// round 13
// baseline (speedup 1.0000x reference)
#include <cuda_runtime.h>
#include <cuda_fp16.h>
#include <cstdint>

// SynergyGraph: out[b,s,t] = (W[seq[b,s]] . W[seq[b,t]]) / sqrt(64)
// B=16, S=2048, D=64, VOCAB=32000. Output fp32 [16,2048,2048].
//
// fp16 single-pass mma.sync m16n8k16, fp32 accum (rel err ~3e-4).
// Kernel 1 materializes gathered fp16 table E[16][2048][64] once; kernel 2
// is a symmetric tiled GEMM over lower-triangle 128x128 tiles with the
// mirror tile written via SMEM transpose staging.
//
// R13: merge the two 64-col half-CTAs into one 128x128 CTA (512 threads,
// 16 warps = 4Mx4N, warp tile 32x32 unchanged). Cuts gather traffic -33%
// (A rows loaded once per pair, not twice), halves CTA count / pair-decode
// alu, and diagonal tiles need NO B gather (B tile == A tile). 64 regs x
// 512thr x 2 CTAs = full RF -> 32 warps/SM, same as before.

#define DEVFN __device__ __forceinline__

static constexpr int BATCH  = 16;
static constexpr int SEQ    = 2048;
static constexpr int TILE   = 128;
static constexpr int NT     = SEQ / TILE;            // 16
static constexpr int NPAIRS = NT * (NT + 1) / 2;     // 136
static constexpr int THREADS = 512;

static constexpr int ROW_BYTES = 144;                // 64 fp16 padded to 72
static constexpr int A_BYTES = 128 * ROW_BYTES;      // 18432
static constexpr int OFF_A = 0;
static constexpr int OFF_B = A_BYTES;                // B: 128 rows
// transpose staging: 128 cols x 128 rows fp32, stride LDT=132 (conflict-free)
static constexpr int LDT = 132;
static constexpr int SMEM_BYTES = 128 * LDT * 4;     // 67584 (> tiles 36864)

// gathered fp16 embeddings: [16][2048][64] = 4MB device scratch
__device__ __align__(16) __half g_emb[BATCH * SEQ * 64];

DEVFN uint32_t smem_u32(const void* p) {
    uint32_t a;
    asm("{ .reg .u64 t; cvta.to.shared.u64 t, %1; cvt.u32.u64 %0, t; }"
        : "=r"(a) : "l"(p));
    return a;
}

DEVFN void sts128(uint32_t addr, uint4 v) {
    asm volatile("st.shared.v4.b32 [%0], {%1, %2, %3, %4};"
                 :: "r"(addr), "r"(v.x), "r"(v.y), "r"(v.z), "r"(v.w) : "memory");
}

DEVFN void ldsm4(uint32_t* r, uint32_t addr) {
    asm volatile("ldmatrix.sync.aligned.m8n8.x4.shared.b16 {%0, %1, %2, %3}, [%4];"
                 : "=r"(r[0]), "=r"(r[1]), "=r"(r[2]), "=r"(r[3]) : "r"(addr));
}

DEVFN void mma16816(float* c, const uint32_t* a, uint32_t b0, uint32_t b1) {
    asm volatile(
        "mma.sync.aligned.m16n8k16.row.col.f32.f16.f16.f32 "
        "{%0, %1, %2, %3}, {%4, %5, %6, %7}, {%8, %9}, {%0, %1, %2, %3};"
        : "+f"(c[0]), "+f"(c[1]), "+f"(c[2]), "+f"(c[3])
        : "r"(a[0]), "r"(a[1]), "r"(a[2]), "r"(a[3]), "r"(b0), "r"(b1));
}

// ---- Kernel 1: gather + fp32->fp16 convert, once per (b,s) row ----
__global__ void __launch_bounds__(256)
build_emb_kernel(const int* __restrict__ seq, const float* __restrict__ weight)
{
    const int id    = blockIdx.x * 256 + threadIdx.x;
    const int row   = id >> 4;          // 0..32767 (= b*2048 + s)
    const int chunk = id & 15;          // 16B fp32 chunk

    const int idx = seq[row];
    const float4 v = reinterpret_cast<const float4*>(weight)[(size_t)idx * 16 + chunk];
    const __half2 h0 = __floats2half2_rn(v.x, v.y);
    const __half2 h1 = __floats2half2_rn(v.z, v.w);
    uint2 u;
    u.x = *reinterpret_cast<const uint32_t*>(&h0);
    u.y = *reinterpret_cast<const uint32_t*>(&h1);
    reinterpret_cast<uint2*>(g_emb)[(size_t)row * 16 + chunk] = u;
}

// ---- Kernel 2: symmetric tiled GEMM from E ----
__global__ void __launch_bounds__(THREADS, 2)
synergy_kernel(float* __restrict__ out)
{
    extern __shared__ char smem_raw[];
    const uint32_t smem = smem_u32(smem_raw);
    float* smem_f = reinterpret_cast<float*>(smem_raw);

    const int tid  = threadIdx.x;
    const int wid  = tid >> 5;
    const int lane = tid & 31;

    // ---- pair decode: p -> (mT, nT), mT >= nT ----
    const int p  = blockIdx.x;
    const int bb = blockIdx.y;
    int mT = (int)((sqrtf(8.0f * (float)p + 1.0f) - 1.0f) * 0.5f);
    while ((mT + 1) * (mT + 2) / 2 <= p) ++mT;
    while (mT * (mT + 1) / 2 > p) --mT;
    const int nT = p - mT * (mT + 1) / 2;
    const bool diag = (mT == nT);

    // ---- Coalesced tile load from E (128B fp16 rows) ----
    // 8 lanes per row (16B chunks), 64 rows per iter of 512 threads.
    // iters 0..1: A rows (128). iters 2..3: B rows (128) — skipped when diag.
    {
        const int chunk = tid & 7;
        const int rsub  = tid >> 3;          // 0..63
        const uint4* E4 = reinterpret_cast<const uint4*>(g_emb);
        const size_t ebase = (size_t)bb * SEQ;
        const int nIter = diag ? 2 : 4;

        #pragma unroll
        for (int iter = 0; iter < 4; ++iter) {
            if (iter >= nIter) break;
            const int row256 = iter * 64 + rsub;       // 0..255
            const bool isA   = (row256 < 128);
            const int  row   = row256 & 127;
            const int  pos   = (isA ? mT : nT) * TILE + row;

            const uint4 v = E4[(ebase + pos) * 8 + chunk];

            const uint32_t base = smem + (isA ? OFF_A : OFF_B)
                                + (uint32_t)row * ROW_BYTES + (uint32_t)chunk * 16;
            sts128(base, v);
        }
    }
    __syncthreads();

    // ---- Warp tiling: 16 warps = 4 (M) x 4 (N); warp tile 32x32 ----
    const int wm = (wid >> 2) * 32;   // 0,32,64,96
    const int wn = (wid & 3) * 32;    // 0,32,64,96

    float acc[2][4][4];
    #pragma unroll
    for (int mi = 0; mi < 2; ++mi)
        #pragma unroll
        for (int nj = 0; nj < 4; ++nj)
            #pragma unroll
            for (int q = 0; q < 4; ++q) acc[mi][nj][q] = 0.f;

    const int a_row  = lane & 15;
    const int a_col  = (lane >> 4) * 8;
    const int b_row  = (lane & 7) + ((lane >> 4) * 8);
    const int b_col  = ((lane >> 3) & 1) * 8;

    const uint32_t a_base =
        smem + OFF_A + (uint32_t)(wm + a_row) * ROW_BYTES + (uint32_t)a_col * 2;
    // diagonal: B tile IS the A tile
    const uint32_t b_tile = diag ? (smem + OFF_A) : (smem + OFF_B);
    const uint32_t b_base =
        b_tile + (uint32_t)(wn + b_row) * ROW_BYTES + (uint32_t)b_col * 2;

    #pragma unroll
    for (int k = 0; k < 4; ++k) {           // k16 steps over K=64
        const uint32_t koff = (uint32_t)(k * 16) * 2;

        uint32_t bf[2][4];
        #pragma unroll
        for (int bj = 0; bj < 2; ++bj)
            ldsm4(bf[bj], b_base + koff + (uint32_t)(bj * 16) * ROW_BYTES);

        #pragma unroll
        for (int mi = 0; mi < 2; ++mi) {
            uint32_t af[4];
            ldsm4(af, a_base + koff + (uint32_t)(mi * 16) * ROW_BYTES);

            #pragma unroll
            for (int nj = 0; nj < 4; ++nj) {
                const uint32_t* bp = &bf[nj >> 1][(nj & 1) * 2];
                mma16816(acc[mi][nj], af, bp[0], bp[1]);
            }
        }
    }

    const int g = lane >> 2;     // row within 8
    const int t = lane & 3;      // col pair

    // ---- Off-diagonal: stage transposed tile into SMEM (reuses gather smem)
    if (!diag) {
        __syncthreads();   // all ldsm reads of gather smem complete
        // smem_t[c][r]: word stride 132 -> bank = 8t + g + const, conflict-free
        #pragma unroll
        for (int mi = 0; mi < 2; ++mi) {
            #pragma unroll
            for (int nj = 0; nj < 4; ++nj) {
                #pragma unroll
                for (int h = 0; h < 2; ++h) {
                    const int row = wm + mi * 16 + 8 * h + g;
                    const int c0  = wn + nj * 8 + 2 * t;
                    smem_f[(c0 + 0) * LDT + row] = acc[mi][nj][2 * h + 0] * 0.125f;
                    smem_f[(c0 + 1) * LDT + row] = acc[mi][nj][2 * h + 1] * 0.125f;
                }
            }
        }
    }

    // ---- Direct tile store (streaming): out[b, mT*128+row, nT*128+col]
    {
        float* obase = out + ((size_t)bb * SEQ + (size_t)(mT * TILE + wm + g)) * SEQ
                           + (size_t)(nT * TILE + wn + 2 * t);
        #pragma unroll
        for (int mi = 0; mi < 2; ++mi) {
            #pragma unroll
            for (int h = 0; h < 2; ++h) {
                float* rowp = obase + (size_t)(mi * 16 + 8 * h) * SEQ;
                #pragma unroll
                for (int nj = 0; nj < 4; ++nj) {
                    float2 v;
                    v.x = acc[mi][nj][2 * h + 0] * 0.125f;
                    v.y = acc[mi][nj][2 * h + 1] * 0.125f;
                    __stcs(reinterpret_cast<float2*>(rowp + nj * 8), v);
                }
            }
        }
    }

    // ---- Mirrored tile (streaming): out[b, nT*128+c, mT*128+r] from SMEM
    if (!diag) {
        __syncthreads();
        float* obase = out + ((size_t)bb * SEQ + (size_t)(nT * TILE)) * SEQ
                           + (size_t)(mT * TILE);
        // 128 rows x 32 float4 = 4096 float4 / 512 threads = 8 iters
        #pragma unroll
        for (int i = 0; i < 8; ++i) {
            const int id = i * THREADS + tid;
            const int r  = id >> 5;          // 0..127: row of mirrored tile
            const int c4 = id & 31;          // float4 index within row
            const float4 v = *reinterpret_cast<const float4*>(smem_f + r * LDT + c4 * 4);
            __stcs(reinterpret_cast<float4*>(obase + (size_t)r * SEQ + c4 * 4), v);
        }
    }
}

extern "C" void kernel_launch(void* const* d_in, const int* in_sizes, int n_in,
                              void* d_out, int out_size)
{
    const int*   seq    = (const int*)d_in[0];    // [16, 2048] int32
    const float* weight = (const float*)d_in[1];  // [32000, 64] fp32
    float*       out    = (float*)d_out;          // [16, 2048, 2048] fp32

    (void)in_sizes; (void)n_in; (void)out_size;

    cudaFuncSetAttribute(synergy_kernel,
                         cudaFuncAttributeMaxDynamicSharedMemorySize, SMEM_BYTES);

    // Kernel 1: materialize fp16 embedding table (16*2048 rows x 16 chunks)
    build_emb_kernel<<<(BATCH * SEQ * 16) / 256, 256>>>(seq, weight);

    // Kernel 2: symmetric GEMM, one CTA per lower-triangle 128x128 tile
    dim3 grid(NPAIRS, BATCH, 1);   // (136 pairs, 16 batches)
    synergy_kernel<<<grid, THREADS, SMEM_BYTES>>>(out);
}

// round 14
// speedup vs baseline: 1.0288x; 1.0288x over previous
#include <cuda_runtime.h>
#include <cuda_fp16.h>
#include <cstdint>

// SynergyGraph: out[b,s,t] = (W[seq[b,s]] . W[seq[b,t]]) / sqrt(64)
// B=16, S=2048, D=64, VOCAB=32000. Output fp32 [16,2048,2048].
//
// fp16 single-pass mma.sync m16n8k16, fp32 accum (rel err ~3e-4).
// Kernel 1 materializes gathered fp16 table E[16][2048][64] once; kernel 2
// is a symmetric tiled GEMM (lower-triangle pairs, 128x64 CTA tiles, 256
// threads, 4 CTAs/SM) with the mirror tile via SMEM transpose staging.
//
// R14: R13's 512-thread merge regressed -> revert to R12 shape. Add:
// (a) direct STG before the staging sync (overlap store drain with other
//     warps' mainloop tails), (b) cp.async gather from E (no LDG->STS reg
//     round-trip), (c) build_emb with 4 chunks/thread (MLP=4).

#define DEVFN __device__ __forceinline__

static constexpr int BATCH  = 16;
static constexpr int SEQ    = 2048;
static constexpr int TILE   = 128;
static constexpr int NT     = SEQ / TILE;            // 16
static constexpr int NPAIRS = NT * (NT + 1) / 2;     // 136

static constexpr int ROW_BYTES = 144;                // 64 fp16 padded to 72
static constexpr int A_BYTES = 128 * ROW_BYTES;      // 18432
static constexpr int OFF_A = 0;
static constexpr int OFF_B = A_BYTES;
// transpose staging: 64 cols x 128 rows fp32, LDT=132 pad (conflict-free)
static constexpr int LDT = 132;
static constexpr int SMEM_BYTES = 64 * LDT * 4;      // 33792 (> tiles 27648)

// gathered fp16 embeddings: [16][2048][64] = 4MB device scratch
__device__ __align__(16) __half g_emb[BATCH * SEQ * 64];

DEVFN uint32_t smem_u32(const void* p) {
    uint32_t a;
    asm("{ .reg .u64 t; cvta.to.shared.u64 t, %1; cvt.u32.u64 %0, t; }"
        : "=r"(a) : "l"(p));
    return a;
}

DEVFN void cp_async16(uint32_t dst, const void* src) {
    asm volatile("cp.async.ca.shared.global [%0], [%1], 16;"
                 :: "r"(dst), "l"(src) : "memory");
}

DEVFN void ldsm4(uint32_t* r, uint32_t addr) {
    asm volatile("ldmatrix.sync.aligned.m8n8.x4.shared.b16 {%0, %1, %2, %3}, [%4];"
                 : "=r"(r[0]), "=r"(r[1]), "=r"(r[2]), "=r"(r[3]) : "r"(addr));
}

DEVFN void mma16816(float* c, const uint32_t* a, uint32_t b0, uint32_t b1) {
    asm volatile(
        "mma.sync.aligned.m16n8k16.row.col.f32.f16.f16.f32 "
        "{%0, %1, %2, %3}, {%4, %5, %6, %7}, {%8, %9}, {%0, %1, %2, %3};"
        : "+f"(c[0]), "+f"(c[1]), "+f"(c[2]), "+f"(c[3])
        : "r"(a[0]), "r"(a[1]), "r"(a[2]), "r"(a[3]), "r"(b0), "r"(b1));
}

// ---- Kernel 1: gather + fp32->fp16 convert, 4 chunks per thread (MLP=4) ----
__global__ void __launch_bounds__(256)
build_emb_kernel(const int* __restrict__ seq, const float* __restrict__ weight)
{
    const int id0 = blockIdx.x * 256 + threadIdx.x;
    #pragma unroll
    for (int j = 0; j < 4; ++j) {
        const int id    = id0 + j * (BATCH * SEQ * 16 / 4);   // 131072 stride
        const int row   = id >> 4;
        const int chunk = id & 15;

        const int idx = seq[row];
        const float4 v = reinterpret_cast<const float4*>(weight)[(size_t)idx * 16 + chunk];
        const __half2 h0 = __floats2half2_rn(v.x, v.y);
        const __half2 h1 = __floats2half2_rn(v.z, v.w);
        uint2 u;
        u.x = *reinterpret_cast<const uint32_t*>(&h0);
        u.y = *reinterpret_cast<const uint32_t*>(&h1);
        reinterpret_cast<uint2*>(g_emb)[(size_t)row * 16 + chunk] = u;
    }
}

// ---- Kernel 2: symmetric tiled GEMM from E ----
__global__ void __launch_bounds__(256, 4)
synergy_kernel(float* __restrict__ out)
{
    extern __shared__ char smem_raw[];
    const uint32_t smem = smem_u32(smem_raw);
    float* smem_f = reinterpret_cast<float*>(smem_raw);

    const int tid  = threadIdx.x;
    const int wid  = tid >> 5;
    const int lane = tid & 31;

    // ---- pair decode: p -> (mT, nT), mT >= nT; half picks 64-col slice ----
    const int p    = blockIdx.x;
    const int half = blockIdx.y;
    const int bb   = blockIdx.z;
    int mT = (int)((sqrtf(8.0f * (float)p + 1.0f) - 1.0f) * 0.5f);
    while ((mT + 1) * (mT + 2) / 2 <= p) ++mT;
    while (mT * (mT + 1) / 2 > p) --mT;
    const int nT = p - mT * (mT + 1) / 2;
    const int ncol0 = nT * TILE + half * 64;   // output col base of this CTA
    const bool diag = (mT == nT);

    // ---- Tile load from E via cp.async (128B fp16 rows) ----
    // 8 lanes per row (16B chunks), 32 rows per iter of 256 threads.
    // iters 0..3: A rows (128). iters 4..5: B rows (64) — skipped when diag.
    {
        const int chunk = tid & 7;           // 16B chunk of the 128B fp16 row
        const int rsub  = tid >> 3;          // 0..31
        const size_t ebase = (size_t)bb * SEQ;
        const int nIter = diag ? 4 : 6;

        #pragma unroll
        for (int iter = 0; iter < 6; ++iter) {
            if (iter >= nIter) break;
            const int row192 = iter * 32 + rsub;       // 0..191
            const bool isA   = (row192 < 128);
            const int  row   = isA ? row192 : (row192 - 128);
            const int  pos   = isA ? (mT * TILE + row192)
                                   : (ncol0 + row192 - 128);

            const uint32_t dst = smem + (isA ? OFF_A : OFF_B)
                               + (uint32_t)row * ROW_BYTES + (uint32_t)chunk * 16;
            cp_async16(dst, g_emb + (ebase + pos) * 64 + chunk * 8);
        }
        asm volatile("cp.async.commit_group;" ::: "memory");
        asm volatile("cp.async.wait_group 0;" ::: "memory");
    }
    __syncthreads();

    // ---- Warp tiling: 8 warps = 4 (M) x 2 (N); warp tile 32x32 ----
    const int wm = (wid >> 1) * 32;   // 0,32,64,96
    const int wn = (wid & 1) * 32;    // 0,32

    float acc[2][4][4];
    #pragma unroll
    for (int mi = 0; mi < 2; ++mi)
        #pragma unroll
        for (int nj = 0; nj < 4; ++nj)
            #pragma unroll
            for (int q = 0; q < 4; ++q) acc[mi][nj][q] = 0.f;

    const int a_row  = lane & 15;
    const int a_col  = (lane >> 4) * 8;
    const int b_row  = (lane & 7) + ((lane >> 4) * 8);
    const int b_col  = ((lane >> 3) & 1) * 8;

    const uint32_t a_base =
        smem + OFF_A + (uint32_t)(wm + a_row) * ROW_BYTES + (uint32_t)a_col * 2;
    // diagonal: B tile aliases rows half*64.. of the A tile
    const uint32_t b_tile = diag ? (smem + OFF_A + (uint32_t)(half * 64) * ROW_BYTES)
                                 : (smem + OFF_B);
    const uint32_t b_base =
        b_tile + (uint32_t)(wn + b_row) * ROW_BYTES + (uint32_t)b_col * 2;

    #pragma unroll
    for (int k = 0; k < 4; ++k) {           // k16 steps over K=64
        const uint32_t koff = (uint32_t)(k * 16) * 2;

        uint32_t bf[2][4];
        #pragma unroll
        for (int bj = 0; bj < 2; ++bj)
            ldsm4(bf[bj], b_base + koff + (uint32_t)(bj * 16) * ROW_BYTES);

        #pragma unroll
        for (int mi = 0; mi < 2; ++mi) {
            uint32_t af[4];
            ldsm4(af, a_base + koff + (uint32_t)(mi * 16) * ROW_BYTES);

            #pragma unroll
            for (int nj = 0; nj < 4; ++nj) {
                const uint32_t* bp = &bf[nj >> 1][(nj & 1) * 2];
                mma16816(acc[mi][nj], af, bp[0], bp[1]);
            }
        }
    }

    const int g = lane >> 2;     // row within 8
    const int t = lane & 3;      // col pair

    // ---- Direct tile store FIRST (register-only; overlaps with other warps'
    //      mainloop tails — no sync needed before this)
    {
        float* obase = out + ((size_t)bb * SEQ + (size_t)(mT * TILE + wm + g)) * SEQ
                           + (size_t)(ncol0 + wn + 2 * t);
        #pragma unroll
        for (int mi = 0; mi < 2; ++mi) {
            #pragma unroll
            for (int h = 0; h < 2; ++h) {
                float* rowp = obase + (size_t)(mi * 16 + 8 * h) * SEQ;
                #pragma unroll
                for (int nj = 0; nj < 4; ++nj) {
                    float2 v;
                    v.x = acc[mi][nj][2 * h + 0] * 0.125f;
                    v.y = acc[mi][nj][2 * h + 1] * 0.125f;
                    __stcs(reinterpret_cast<float2*>(rowp + nj * 8), v);
                }
            }
        }
    }

    // ---- Off-diagonal: transpose-stage (reuses gather smem) then drain mirror
    if (!diag) {
        __syncthreads();   // all ldsm reads of gather smem complete
        // smem_t[c][r]: bank = (4c + r) mod 32 = 8t + g + const -> conflict-free
        #pragma unroll
        for (int mi = 0; mi < 2; ++mi) {
            #pragma unroll
            for (int nj = 0; nj < 4; ++nj) {
                #pragma unroll
                for (int h = 0; h < 2; ++h) {
                    const int row = wm + mi * 16 + 8 * h + g;
                    const int c0  = wn + nj * 8 + 2 * t;
                    smem_f[(c0 + 0) * LDT + row] = acc[mi][nj][2 * h + 0] * 0.125f;
                    smem_f[(c0 + 1) * LDT + row] = acc[mi][nj][2 * h + 1] * 0.125f;
                }
            }
        }
        __syncthreads();
        // mirror: out[b, ncol0+c, mT*128+r], coalesced float4 rows
        float* obase = out + ((size_t)bb * SEQ + (size_t)ncol0) * SEQ
                           + (size_t)(mT * TILE);
        #pragma unroll
        for (int i = 0; i < 8; ++i) {
            const int id = i * 256 + tid;
            const int r  = id >> 5;          // 0..63: row of mirrored tile
            const int c4 = id & 31;          // float4 index within row
            const float4 v = *reinterpret_cast<const float4*>(smem_f + r * LDT + c4 * 4);
            __stcs(reinterpret_cast<float4*>(obase + (size_t)r * SEQ + c4 * 4), v);
        }
    }
}

extern "C" void kernel_launch(void* const* d_in, const int* in_sizes, int n_in,
                              void* d_out, int out_size)
{
    const int*   seq    = (const int*)d_in[0];    // [16, 2048] int32
    const float* weight = (const float*)d_in[1];  // [32000, 64] fp32
    float*       out    = (float*)d_out;          // [16, 2048, 2048] fp32

    (void)in_sizes; (void)n_in; (void)out_size;

    cudaFuncSetAttribute(synergy_kernel,
                         cudaFuncAttributeMaxDynamicSharedMemorySize, SMEM_BYTES);

    // Kernel 1: materialize fp16 embedding table (4 chunks per thread)
    build_emb_kernel<<<(BATCH * SEQ * 16) / 256 / 4, 256>>>(seq, weight);

    // Kernel 2: symmetric GEMM
    dim3 grid(NPAIRS, 2, BATCH);   // (136 pairs, 2 halves, 16 batches)
    synergy_kernel<<<grid, 256, SMEM_BYTES>>>(out);
}

// round 15
// speedup vs baseline: 1.1001x; 1.0693x over previous
#include <cuda_runtime.h>
#include <cuda_fp16.h>
#include <cstdint>

// SynergyGraph: out[b,s,t] = (W[seq[b,s]] . W[seq[b,t]]) / sqrt(64)
// B=16, S=2048, D=64, VOCAB=32000. Output fp32 [16,2048,2048].
//
// fp16 single-pass mma.sync m16n8k16, fp32 accum (rel err ~3e-4).
// Kernel 1 materializes gathered fp16 table E[16][2048][64] once; kernel 2
// is a symmetric tiled GEMM (lower-triangle pairs, 128x64 CTA tiles, 256
// threads, 4 CTAs/SM) with the mirror tile via SMEM transpose staging.
//
// R15: direct-tile stores merged to float4 via lane shuffles. Fragment cols
// {2t,2t+1} pair-exchange with shfl_xor(1): even lanes store nj{0,1}, odd
// lanes nj{2,3} as STG.128 -> direct-store L1 wavefronts halved (1024->~512
// per CTA, -14% total L1 traffic), no extra barriers.

#define DEVFN __device__ __forceinline__

static constexpr int BATCH  = 16;
static constexpr int SEQ    = 2048;
static constexpr int TILE   = 128;
static constexpr int NT     = SEQ / TILE;            // 16
static constexpr int NPAIRS = NT * (NT + 1) / 2;     // 136

static constexpr int ROW_BYTES = 144;                // 64 fp16 padded to 72
static constexpr int A_BYTES = 128 * ROW_BYTES;      // 18432
static constexpr int OFF_A = 0;
static constexpr int OFF_B = A_BYTES;
// transpose staging: 64 cols x 128 rows fp32, LDT=132 pad (conflict-free)
static constexpr int LDT = 132;
static constexpr int SMEM_BYTES = 64 * LDT * 4;      // 33792 (> tiles 27648)

// gathered fp16 embeddings: [16][2048][64] = 4MB device scratch
__device__ __align__(16) __half g_emb[BATCH * SEQ * 64];

DEVFN uint32_t smem_u32(const void* p) {
    uint32_t a;
    asm("{ .reg .u64 t; cvta.to.shared.u64 t, %1; cvt.u32.u64 %0, t; }"
        : "=r"(a) : "l"(p));
    return a;
}

DEVFN void cp_async16(uint32_t dst, const void* src) {
    asm volatile("cp.async.ca.shared.global [%0], [%1], 16;"
                 :: "r"(dst), "l"(src) : "memory");
}

DEVFN void ldsm4(uint32_t* r, uint32_t addr) {
    asm volatile("ldmatrix.sync.aligned.m8n8.x4.shared.b16 {%0, %1, %2, %3}, [%4];"
                 : "=r"(r[0]), "=r"(r[1]), "=r"(r[2]), "=r"(r[3]) : "r"(addr));
}

DEVFN void mma16816(float* c, const uint32_t* a, uint32_t b0, uint32_t b1) {
    asm volatile(
        "mma.sync.aligned.m16n8k16.row.col.f32.f16.f16.f32 "
        "{%0, %1, %2, %3}, {%4, %5, %6, %7}, {%8, %9}, {%0, %1, %2, %3};"
        : "+f"(c[0]), "+f"(c[1]), "+f"(c[2]), "+f"(c[3])
        : "r"(a[0]), "r"(a[1]), "r"(a[2]), "r"(a[3]), "r"(b0), "r"(b1));
}

// ---- Kernel 1: gather + fp32->fp16 convert, 4 chunks per thread (MLP=4) ----
__global__ void __launch_bounds__(256)
build_emb_kernel(const int* __restrict__ seq, const float* __restrict__ weight)
{
    const int id0 = blockIdx.x * 256 + threadIdx.x;
    #pragma unroll
    for (int j = 0; j < 4; ++j) {
        const int id    = id0 + j * (BATCH * SEQ * 16 / 4);
        const int row   = id >> 4;
        const int chunk = id & 15;

        const int idx = seq[row];
        const float4 v = reinterpret_cast<const float4*>(weight)[(size_t)idx * 16 + chunk];
        const __half2 h0 = __floats2half2_rn(v.x, v.y);
        const __half2 h1 = __floats2half2_rn(v.z, v.w);
        uint2 u;
        u.x = *reinterpret_cast<const uint32_t*>(&h0);
        u.y = *reinterpret_cast<const uint32_t*>(&h1);
        reinterpret_cast<uint2*>(g_emb)[(size_t)row * 16 + chunk] = u;
    }
}

// ---- Kernel 2: symmetric tiled GEMM from E ----
__global__ void __launch_bounds__(256, 4)
synergy_kernel(float* __restrict__ out)
{
    extern __shared__ char smem_raw[];
    const uint32_t smem = smem_u32(smem_raw);
    float* smem_f = reinterpret_cast<float*>(smem_raw);

    const int tid  = threadIdx.x;
    const int wid  = tid >> 5;
    const int lane = tid & 31;

    // ---- pair decode: p -> (mT, nT), mT >= nT; half picks 64-col slice ----
    const int p    = blockIdx.x;
    const int half = blockIdx.y;
    const int bb   = blockIdx.z;
    int mT = (int)((sqrtf(8.0f * (float)p + 1.0f) - 1.0f) * 0.5f);
    while ((mT + 1) * (mT + 2) / 2 <= p) ++mT;
    while (mT * (mT + 1) / 2 > p) --mT;
    const int nT = p - mT * (mT + 1) / 2;
    const int ncol0 = nT * TILE + half * 64;   // output col base of this CTA
    const bool diag = (mT == nT);

    // ---- Tile load from E via cp.async (128B fp16 rows) ----
    {
        const int chunk = tid & 7;
        const int rsub  = tid >> 3;          // 0..31
        const size_t ebase = (size_t)bb * SEQ;
        const int nIter = diag ? 4 : 6;

        #pragma unroll
        for (int iter = 0; iter < 6; ++iter) {
            if (iter >= nIter) break;
            const int row192 = iter * 32 + rsub;       // 0..191
            const bool isA   = (row192 < 128);
            const int  row   = isA ? row192 : (row192 - 128);
            const int  pos   = isA ? (mT * TILE + row192)
                                   : (ncol0 + row192 - 128);

            const uint32_t dst = smem + (isA ? OFF_A : OFF_B)
                               + (uint32_t)row * ROW_BYTES + (uint32_t)chunk * 16;
            cp_async16(dst, g_emb + (ebase + pos) * 64 + chunk * 8);
        }
        asm volatile("cp.async.commit_group;" ::: "memory");
        asm volatile("cp.async.wait_group 0;" ::: "memory");
    }
    __syncthreads();

    // ---- Warp tiling: 8 warps = 4 (M) x 2 (N); warp tile 32x32 ----
    const int wm = (wid >> 1) * 32;   // 0,32,64,96
    const int wn = (wid & 1) * 32;    // 0,32

    float acc[2][4][4];
    #pragma unroll
    for (int mi = 0; mi < 2; ++mi)
        #pragma unroll
        for (int nj = 0; nj < 4; ++nj)
            #pragma unroll
            for (int q = 0; q < 4; ++q) acc[mi][nj][q] = 0.f;

    const int a_row  = lane & 15;
    const int a_col  = (lane >> 4) * 8;
    const int b_row  = (lane & 7) + ((lane >> 4) * 8);
    const int b_col  = ((lane >> 3) & 1) * 8;

    const uint32_t a_base =
        smem + OFF_A + (uint32_t)(wm + a_row) * ROW_BYTES + (uint32_t)a_col * 2;
    const uint32_t b_tile = diag ? (smem + OFF_A + (uint32_t)(half * 64) * ROW_BYTES)
                                 : (smem + OFF_B);
    const uint32_t b_base =
        b_tile + (uint32_t)(wn + b_row) * ROW_BYTES + (uint32_t)b_col * 2;

    #pragma unroll
    for (int k = 0; k < 4; ++k) {           // k16 steps over K=64
        const uint32_t koff = (uint32_t)(k * 16) * 2;

        uint32_t bf[2][4];
        #pragma unroll
        for (int bj = 0; bj < 2; ++bj)
            ldsm4(bf[bj], b_base + koff + (uint32_t)(bj * 16) * ROW_BYTES);

        #pragma unroll
        for (int mi = 0; mi < 2; ++mi) {
            uint32_t af[4];
            ldsm4(af, a_base + koff + (uint32_t)(mi * 16) * ROW_BYTES);

            #pragma unroll
            for (int nj = 0; nj < 4; ++nj) {
                const uint32_t* bp = &bf[nj >> 1][(nj & 1) * 2];
                mma16816(acc[mi][nj], af, bp[0], bp[1]);
            }
        }
    }

    const int g = lane >> 2;     // row within 8
    const int t = lane & 3;      // col pair
    const bool oddl = (t & 1);

    // ---- Direct tile store FIRST: shfl-merge lane pairs into float4 STG.128.
    // Lane t covers within-block cols {2t,2t+1}; pair (t, t^1) covers a
    // 4-col run at nj*8 + 4*(t>>1). Even lanes store nj{0,1}, odd nj{2,3}.
    {
        float* obase = out + ((size_t)bb * SEQ + (size_t)(mT * TILE + wm + g)) * SEQ
                           + (size_t)(ncol0 + wn + 4 * (t >> 1));
        #pragma unroll
        for (int mi = 0; mi < 2; ++mi) {
            #pragma unroll
            for (int h = 0; h < 2; ++h) {
                float2 vv[4];
                #pragma unroll
                for (int nj = 0; nj < 4; ++nj) {
                    vv[nj].x = acc[mi][nj][2 * h + 0] * 0.125f;
                    vv[nj].y = acc[mi][nj][2 * h + 1] * 0.125f;
                }
                // each lane sends what its partner needs
                float2 s0 = oddl ? vv[0] : vv[2];
                float2 s1 = oddl ? vv[1] : vv[3];
                float2 r0, r1;
                r0.x = __shfl_xor_sync(0xFFFFFFFFu, s0.x, 1);
                r0.y = __shfl_xor_sync(0xFFFFFFFFu, s0.y, 1);
                r1.x = __shfl_xor_sync(0xFFFFFFFFu, s1.x, 1);
                r1.y = __shfl_xor_sync(0xFFFFFFFFu, s1.y, 1);

                float4 o0, o1;
                int njA, njB;
                if (!oddl) {
                    o0 = make_float4(vv[0].x, vv[0].y, r0.x, r0.y); njA = 0;
                    o1 = make_float4(vv[1].x, vv[1].y, r1.x, r1.y); njB = 1;
                } else {
                    o0 = make_float4(r0.x, r0.y, vv[2].x, vv[2].y); njA = 2;
                    o1 = make_float4(r1.x, r1.y, vv[3].x, vv[3].y); njB = 3;
                }
                float* rowp = obase + (size_t)(mi * 16 + 8 * h) * SEQ;
                __stcs(reinterpret_cast<float4*>(rowp + njA * 8), o0);
                __stcs(reinterpret_cast<float4*>(rowp + njB * 8), o1);
            }
        }
    }

    // ---- Off-diagonal: transpose-stage (reuses gather smem) then drain mirror
    if (!diag) {
        __syncthreads();   // all ldsm reads of gather smem complete
        // smem_t[c][r]: bank = (4c + r) mod 32 = 8t + g + const -> conflict-free
        #pragma unroll
        for (int mi = 0; mi < 2; ++mi) {
            #pragma unroll
            for (int nj = 0; nj < 4; ++nj) {
                #pragma unroll
                for (int h = 0; h < 2; ++h) {
                    const int row = wm + mi * 16 + 8 * h + g;
                    const int c0  = wn + nj * 8 + 2 * t;
                    smem_f[(c0 + 0) * LDT + row] = acc[mi][nj][2 * h + 0] * 0.125f;
                    smem_f[(c0 + 1) * LDT + row] = acc[mi][nj][2 * h + 1] * 0.125f;
                }
            }
        }
        __syncthreads();
        // mirror: out[b, ncol0+c, mT*128+r], coalesced float4 rows
        float* obase = out + ((size_t)bb * SEQ + (size_t)ncol0) * SEQ
                           + (size_t)(mT * TILE);
        #pragma unroll
        for (int i = 0; i < 8; ++i) {
            const int id = i * 256 + tid;
            const int r  = id >> 5;          // 0..63: row of mirrored tile
            const int c4 = id & 31;          // float4 index within row
            const float4 v = *reinterpret_cast<const float4*>(smem_f + r * LDT + c4 * 4);
            __stcs(reinterpret_cast<float4*>(obase + (size_t)r * SEQ + c4 * 4), v);
        }
    }
}

extern "C" void kernel_launch(void* const* d_in, const int* in_sizes, int n_in,
                              void* d_out, int out_size)
{
    const int*   seq    = (const int*)d_in[0];    // [16, 2048] int32
    const float* weight = (const float*)d_in[1];  // [32000, 64] fp32
    float*       out    = (float*)d_out;          // [16, 2048, 2048] fp32

    (void)in_sizes; (void)n_in; (void)out_size;

    cudaFuncSetAttribute(synergy_kernel,
                         cudaFuncAttributeMaxDynamicSharedMemorySize, SMEM_BYTES);

    // Kernel 1: materialize fp16 embedding table (4 chunks per thread)
    build_emb_kernel<<<(BATCH * SEQ * 16) / 256 / 4, 256>>>(seq, weight);

    // Kernel 2: symmetric GEMM
    dim3 grid(NPAIRS, 2, BATCH);   // (136 pairs, 2 halves, 16 batches)
    synergy_kernel<<<grid, 256, SMEM_BYTES>>>(out);
}

// round 16
// speedup vs baseline: 1.1060x; 1.0054x over previous
#include <cuda_runtime.h>
#include <cuda_fp16.h>
#include <cstdint>

// SynergyGraph: out[b,s,t] = (W[seq[b,s]] . W[seq[b,t]]) / sqrt(64)
// B=16, S=2048, D=64, VOCAB=32000. Output fp32 [16,2048,2048].
//
// fp16 single-pass mma.sync m16n8k16, fp32 accum (rel err ~3e-4).
// Kernel 1 materializes gathered fp16 table E[16][2048][64] once; kernel 2
// is a symmetric tiled GEMM (lower-triangle pairs, 128x64 CTA tiles, 256
// threads, 4 CTAs/SM): direct tile stored via shfl-merged STG.128, mirror
// tile via SMEM transpose staging.
//
// R16: heavy-first CTA ordering. Off-diagonal CTAs (2 output tiles each)
// take p<120; light diagonal CTAs (1 tile) take p>=120 and pack the
// ragged final wave (4352 CTAs = 7.35 waves of 592).

#define DEVFN __device__ __forceinline__

static constexpr int BATCH  = 16;
static constexpr int SEQ    = 2048;
static constexpr int TILE   = 128;
static constexpr int NT     = SEQ / TILE;            // 16
static constexpr int NOFF   = NT * (NT - 1) / 2;     // 120 strict-lower pairs
static constexpr int NPAIRS = NOFF + NT;             // 136

static constexpr int ROW_BYTES = 144;                // 64 fp16 padded to 72
static constexpr int A_BYTES = 128 * ROW_BYTES;      // 18432
static constexpr int OFF_A = 0;
static constexpr int OFF_B = A_BYTES;
// transpose staging: 64 cols x 128 rows fp32, LDT=132 pad (conflict-free)
static constexpr int LDT = 132;
static constexpr int SMEM_BYTES = 64 * LDT * 4;      // 33792 (> tiles 27648)

// gathered fp16 embeddings: [16][2048][64] = 4MB device scratch
__device__ __align__(16) __half g_emb[BATCH * SEQ * 64];

DEVFN uint32_t smem_u32(const void* p) {
    uint32_t a;
    asm("{ .reg .u64 t; cvta.to.shared.u64 t, %1; cvt.u32.u64 %0, t; }"
        : "=r"(a) : "l"(p));
    return a;
}

DEVFN void cp_async16(uint32_t dst, const void* src) {
    asm volatile("cp.async.ca.shared.global [%0], [%1], 16;"
                 :: "r"(dst), "l"(src) : "memory");
}

DEVFN void ldsm4(uint32_t* r, uint32_t addr) {
    asm volatile("ldmatrix.sync.aligned.m8n8.x4.shared.b16 {%0, %1, %2, %3}, [%4];"
                 : "=r"(r[0]), "=r"(r[1]), "=r"(r[2]), "=r"(r[3]) : "r"(addr));
}

DEVFN void mma16816(float* c, const uint32_t* a, uint32_t b0, uint32_t b1) {
    asm volatile(
        "mma.sync.aligned.m16n8k16.row.col.f32.f16.f16.f32 "
        "{%0, %1, %2, %3}, {%4, %5, %6, %7}, {%8, %9}, {%0, %1, %2, %3};"
        : "+f"(c[0]), "+f"(c[1]), "+f"(c[2]), "+f"(c[3])
        : "r"(a[0]), "r"(a[1]), "r"(a[2]), "r"(a[3]), "r"(b0), "r"(b1));
}

// ---- Kernel 1: gather + fp32->fp16 convert, 4 chunks per thread (MLP=4) ----
__global__ void __launch_bounds__(256)
build_emb_kernel(const int* __restrict__ seq, const float* __restrict__ weight)
{
    const int id0 = blockIdx.x * 256 + threadIdx.x;
    #pragma unroll
    for (int j = 0; j < 4; ++j) {
        const int id    = id0 + j * (BATCH * SEQ * 16 / 4);
        const int row   = id >> 4;
        const int chunk = id & 15;

        const int idx = seq[row];
        const float4 v = reinterpret_cast<const float4*>(weight)[(size_t)idx * 16 + chunk];
        const __half2 h0 = __floats2half2_rn(v.x, v.y);
        const __half2 h1 = __floats2half2_rn(v.z, v.w);
        uint2 u;
        u.x = *reinterpret_cast<const uint32_t*>(&h0);
        u.y = *reinterpret_cast<const uint32_t*>(&h1);
        reinterpret_cast<uint2*>(g_emb)[(size_t)row * 16 + chunk] = u;
    }
}

// ---- Kernel 2: symmetric tiled GEMM from E ----
__global__ void __launch_bounds__(256, 4)
synergy_kernel(float* __restrict__ out)
{
    extern __shared__ char smem_raw[];
    const uint32_t smem = smem_u32(smem_raw);
    float* smem_f = reinterpret_cast<float*>(smem_raw);

    const int tid  = threadIdx.x;
    const int wid  = tid >> 5;
    const int lane = tid & 31;

    // ---- pair decode, heavy-first ----
    // p < 120: strict-lower pair (mT > nT), p = mT*(mT-1)/2 + nT
    // p >= 120: diagonal tile mT = nT = p - 120  (light CTAs last -> tail)
    const int p    = blockIdx.x;
    const int half = blockIdx.y;
    const int bb   = blockIdx.z;
    int mT, nT;
    bool diag;
    if (p < NOFF) {
        diag = false;
        mT = (int)((sqrtf(8.0f * (float)p + 1.0f) + 1.0f) * 0.5f);
        while (mT * (mT - 1) / 2 > p) --mT;
        while ((mT + 1) * mT / 2 <= p) ++mT;
        nT = p - mT * (mT - 1) / 2;
    } else {
        diag = true;
        mT = nT = p - NOFF;
    }
    const int ncol0 = nT * TILE + half * 64;   // output col base of this CTA

    // ---- Tile load from E via cp.async (128B fp16 rows) ----
    {
        const int chunk = tid & 7;
        const int rsub  = tid >> 3;          // 0..31
        const size_t ebase = (size_t)bb * SEQ;
        const int nIter = diag ? 4 : 6;

        #pragma unroll
        for (int iter = 0; iter < 6; ++iter) {
            if (iter >= nIter) break;
            const int row192 = iter * 32 + rsub;       // 0..191
            const bool isA   = (row192 < 128);
            const int  row   = isA ? row192 : (row192 - 128);
            const int  pos   = isA ? (mT * TILE + row192)
                                   : (ncol0 + row192 - 128);

            const uint32_t dst = smem + (isA ? OFF_A : OFF_B)
                               + (uint32_t)row * ROW_BYTES + (uint32_t)chunk * 16;
            cp_async16(dst, g_emb + (ebase + pos) * 64 + chunk * 8);
        }
        asm volatile("cp.async.commit_group;" ::: "memory");
        asm volatile("cp.async.wait_group 0;" ::: "memory");
    }
    __syncthreads();

    // ---- Warp tiling: 8 warps = 4 (M) x 2 (N); warp tile 32x32 ----
    const int wm = (wid >> 1) * 32;   // 0,32,64,96
    const int wn = (wid & 1) * 32;    // 0,32

    float acc[2][4][4];
    #pragma unroll
    for (int mi = 0; mi < 2; ++mi)
        #pragma unroll
        for (int nj = 0; nj < 4; ++nj)
            #pragma unroll
            for (int q = 0; q < 4; ++q) acc[mi][nj][q] = 0.f;

    const int a_row  = lane & 15;
    const int a_col  = (lane >> 4) * 8;
    const int b_row  = (lane & 7) + ((lane >> 4) * 8);
    const int b_col  = ((lane >> 3) & 1) * 8;

    const uint32_t a_base =
        smem + OFF_A + (uint32_t)(wm + a_row) * ROW_BYTES + (uint32_t)a_col * 2;
    const uint32_t b_tile = diag ? (smem + OFF_A + (uint32_t)(half * 64) * ROW_BYTES)
                                 : (smem + OFF_B);
    const uint32_t b_base =
        b_tile + (uint32_t)(wn + b_row) * ROW_BYTES + (uint32_t)b_col * 2;

    #pragma unroll
    for (int k = 0; k < 4; ++k) {           // k16 steps over K=64
        const uint32_t koff = (uint32_t)(k * 16) * 2;

        uint32_t bf[2][4];
        #pragma unroll
        for (int bj = 0; bj < 2; ++bj)
            ldsm4(bf[bj], b_base + koff + (uint32_t)(bj * 16) * ROW_BYTES);

        #pragma unroll
        for (int mi = 0; mi < 2; ++mi) {
            uint32_t af[4];
            ldsm4(af, a_base + koff + (uint32_t)(mi * 16) * ROW_BYTES);

            #pragma unroll
            for (int nj = 0; nj < 4; ++nj) {
                const uint32_t* bp = &bf[nj >> 1][(nj & 1) * 2];
                mma16816(acc[mi][nj], af, bp[0], bp[1]);
            }
        }
    }

    const int g = lane >> 2;     // row within 8
    const int t = lane & 3;      // col pair
    const bool oddl = (t & 1);

    // ---- Direct tile store FIRST: shfl-merge lane pairs into float4 STG.128.
    {
        float* obase = out + ((size_t)bb * SEQ + (size_t)(mT * TILE + wm + g)) * SEQ
                           + (size_t)(ncol0 + wn + 4 * (t >> 1));
        #pragma unroll
        for (int mi = 0; mi < 2; ++mi) {
            #pragma unroll
            for (int h = 0; h < 2; ++h) {
                float2 vv[4];
                #pragma unroll
                for (int nj = 0; nj < 4; ++nj) {
                    vv[nj].x = acc[mi][nj][2 * h + 0] * 0.125f;
                    vv[nj].y = acc[mi][nj][2 * h + 1] * 0.125f;
                }
                float2 s0 = oddl ? vv[0] : vv[2];
                float2 s1 = oddl ? vv[1] : vv[3];
                float2 r0, r1;
                r0.x = __shfl_xor_sync(0xFFFFFFFFu, s0.x, 1);
                r0.y = __shfl_xor_sync(0xFFFFFFFFu, s0.y, 1);
                r1.x = __shfl_xor_sync(0xFFFFFFFFu, s1.x, 1);
                r1.y = __shfl_xor_sync(0xFFFFFFFFu, s1.y, 1);

                float4 o0, o1;
                int njA, njB;
                if (!oddl) {
                    o0 = make_float4(vv[0].x, vv[0].y, r0.x, r0.y); njA = 0;
                    o1 = make_float4(vv[1].x, vv[1].y, r1.x, r1.y); njB = 1;
                } else {
                    o0 = make_float4(r0.x, r0.y, vv[2].x, vv[2].y); njA = 2;
                    o1 = make_float4(r1.x, r1.y, vv[3].x, vv[3].y); njB = 3;
                }
                float* rowp = obase + (size_t)(mi * 16 + 8 * h) * SEQ;
                __stcs(reinterpret_cast<float4*>(rowp + njA * 8), o0);
                __stcs(reinterpret_cast<float4*>(rowp + njB * 8), o1);
            }
        }
    }

    // ---- Off-diagonal: transpose-stage (reuses gather smem) then drain mirror
    if (!diag) {
        __syncthreads();   // all ldsm reads of gather smem complete
        // smem_t[c][r]: bank = (4c + r) mod 32 = 8t + g + const -> conflict-free
        #pragma unroll
        for (int mi = 0; mi < 2; ++mi) {
            #pragma unroll
            for (int nj = 0; nj < 4; ++nj) {
                #pragma unroll
                for (int h = 0; h < 2; ++h) {
                    const int row = wm + mi * 16 + 8 * h + g;
                    const int c0  = wn + nj * 8 + 2 * t;
                    smem_f[(c0 + 0) * LDT + row] = acc[mi][nj][2 * h + 0] * 0.125f;
                    smem_f[(c0 + 1) * LDT + row] = acc[mi][nj][2 * h + 1] * 0.125f;
                }
            }
        }
        __syncthreads();
        // mirror: out[b, ncol0+c, mT*128+r], coalesced float4 rows
        float* obase = out + ((size_t)bb * SEQ + (size_t)ncol0) * SEQ
                           + (size_t)(mT * TILE);
        #pragma unroll
        for (int i = 0; i < 8; ++i) {
            const int id = i * 256 + tid;
            const int r  = id >> 5;          // 0..63: row of mirrored tile
            const int c4 = id & 31;          // float4 index within row
            const float4 v = *reinterpret_cast<const float4*>(smem_f + r * LDT + c4 * 4);
            __stcs(reinterpret_cast<float4*>(obase + (size_t)r * SEQ + c4 * 4), v);
        }
    }
}

extern "C" void kernel_launch(void* const* d_in, const int* in_sizes, int n_in,
                              void* d_out, int out_size)
{
    const int*   seq    = (const int*)d_in[0];    // [16, 2048] int32
    const float* weight = (const float*)d_in[1];  // [32000, 64] fp32
    float*       out    = (float*)d_out;          // [16, 2048, 2048] fp32

    (void)in_sizes; (void)n_in; (void)out_size;

    cudaFuncSetAttribute(synergy_kernel,
                         cudaFuncAttributeMaxDynamicSharedMemorySize, SMEM_BYTES);

    // Kernel 1: materialize fp16 embedding table (4 chunks per thread)
    build_emb_kernel<<<(BATCH * SEQ * 16) / 256 / 4, 256>>>(seq, weight);

    // Kernel 2: symmetric GEMM, heavy (off-diag) CTAs first
    dim3 grid(NPAIRS, 2, BATCH);   // (136 pairs, 2 halves, 16 batches)
    synergy_kernel<<<grid, 256, SMEM_BYTES>>>(out);
}

// round 17
// speedup vs baseline: 1.1066x; 1.0006x over previous
#include <cuda_runtime.h>
#include <cuda_fp16.h>
#include <cstdint>

// SynergyGraph: out[b,s,t] = (W[seq[b,s]] . W[seq[b,t]]) / sqrt(64)
// B=16, S=2048, D=64, VOCAB=32000. Output fp32 [16,2048,2048].
//
// fp16 single-pass mma.sync m16n8k16, fp32 accum (rel err ~3e-4).
// Kernel 1 materializes gathered fp16 table E[16][2048][64] once, PRE-SCALED
// by sqrt(1/8) so the MMA product carries the 1/sqrt(64) factor directly.
// Kernel 2: symmetric tiled GEMM (lower-triangle pairs, 128x64 CTA tiles,
// 256 threads, 4 CTAs/SM): direct tile via shfl-merged STG.128, mirror tile
// via SMEM transpose staging. Heavy (off-diag) CTAs scheduled first.
//
// R17: fold the 0.125 scale into the operands (epilogue FMULs deleted);
// build_emb hoists seq-index loads ahead of weight loads. Kernel is at the
// DRAM-write roofline (~5.3 TB/s of pure output writes).

#define DEVFN __device__ __forceinline__

static constexpr int BATCH  = 16;
static constexpr int SEQ    = 2048;
static constexpr int TILE   = 128;
static constexpr int NT     = SEQ / TILE;            // 16
static constexpr int NOFF   = NT * (NT - 1) / 2;     // 120 strict-lower pairs
static constexpr int NPAIRS = NOFF + NT;             // 136

static constexpr int ROW_BYTES = 144;                // 64 fp16 padded to 72
static constexpr int A_BYTES = 128 * ROW_BYTES;      // 18432
static constexpr int OFF_A = 0;
static constexpr int OFF_B = A_BYTES;
// transpose staging: 64 cols x 128 rows fp32, LDT=132 pad (conflict-free)
static constexpr int LDT = 132;
static constexpr int SMEM_BYTES = 64 * LDT * 4;      // 33792 (> tiles 27648)

// sqrt(1/8): operand pre-scale so product carries 1/8
static constexpr float PRESCALE = 0.35355339059327373f;

// gathered fp16 embeddings: [16][2048][64] = 4MB device scratch
__device__ __align__(16) __half g_emb[BATCH * SEQ * 64];

DEVFN uint32_t smem_u32(const void* p) {
    uint32_t a;
    asm("{ .reg .u64 t; cvta.to.shared.u64 t, %1; cvt.u32.u64 %0, t; }"
        : "=r"(a) : "l"(p));
    return a;
}

DEVFN void cp_async16(uint32_t dst, const void* src) {
    asm volatile("cp.async.ca.shared.global [%0], [%1], 16;"
                 :: "r"(dst), "l"(src) : "memory");
}

DEVFN void ldsm4(uint32_t* r, uint32_t addr) {
    asm volatile("ldmatrix.sync.aligned.m8n8.x4.shared.b16 {%0, %1, %2, %3}, [%4];"
                 : "=r"(r[0]), "=r"(r[1]), "=r"(r[2]), "=r"(r[3]) : "r"(addr));
}

DEVFN void mma16816(float* c, const uint32_t* a, uint32_t b0, uint32_t b1) {
    asm volatile(
        "mma.sync.aligned.m16n8k16.row.col.f32.f16.f16.f32 "
        "{%0, %1, %2, %3}, {%4, %5, %6, %7}, {%8, %9}, {%0, %1, %2, %3};"
        : "+f"(c[0]), "+f"(c[1]), "+f"(c[2]), "+f"(c[3])
        : "r"(a[0]), "r"(a[1]), "r"(a[2]), "r"(a[3]), "r"(b0), "r"(b1));
}

// ---- Kernel 1: gather + pre-scale + fp32->fp16 convert, 4 chunks/thread ----
__global__ void __launch_bounds__(256)
build_emb_kernel(const int* __restrict__ seq, const float* __restrict__ weight)
{
    const int id0 = blockIdx.x * 256 + threadIdx.x;

    int rows[4];
    int idxs[4];
    #pragma unroll
    for (int j = 0; j < 4; ++j) {            // batch the index loads (MLP)
        const int id = id0 + j * (BATCH * SEQ * 16 / 4);
        rows[j] = id >> 4;
        idxs[j] = seq[rows[j]];
    }
    #pragma unroll
    for (int j = 0; j < 4; ++j) {
        const int id    = id0 + j * (BATCH * SEQ * 16 / 4);
        const int chunk = id & 15;

        const float4 v = reinterpret_cast<const float4*>(weight)[(size_t)idxs[j] * 16 + chunk];
        const __half2 h0 = __floats2half2_rn(v.x * PRESCALE, v.y * PRESCALE);
        const __half2 h1 = __floats2half2_rn(v.z * PRESCALE, v.w * PRESCALE);
        uint2 u;
        u.x = *reinterpret_cast<const uint32_t*>(&h0);
        u.y = *reinterpret_cast<const uint32_t*>(&h1);
        reinterpret_cast<uint2*>(g_emb)[(size_t)rows[j] * 16 + chunk] = u;
    }
}

// ---- Kernel 2: symmetric tiled GEMM from E ----
__global__ void __launch_bounds__(256, 4)
synergy_kernel(float* __restrict__ out)
{
    extern __shared__ char smem_raw[];
    const uint32_t smem = smem_u32(smem_raw);
    float* smem_f = reinterpret_cast<float*>(smem_raw);

    const int tid  = threadIdx.x;
    const int wid  = tid >> 5;
    const int lane = tid & 31;

    // ---- pair decode, heavy-first ----
    const int p    = blockIdx.x;
    const int half = blockIdx.y;
    const int bb   = blockIdx.z;
    int mT, nT;
    bool diag;
    if (p < NOFF) {
        diag = false;
        mT = (int)((sqrtf(8.0f * (float)p + 1.0f) + 1.0f) * 0.5f);
        while (mT * (mT - 1) / 2 > p) --mT;
        while ((mT + 1) * mT / 2 <= p) ++mT;
        nT = p - mT * (mT - 1) / 2;
    } else {
        diag = true;
        mT = nT = p - NOFF;
    }
    const int ncol0 = nT * TILE + half * 64;   // output col base of this CTA

    // ---- Tile load from E via cp.async (128B fp16 rows) ----
    {
        const int chunk = tid & 7;
        const int rsub  = tid >> 3;          // 0..31
        const size_t ebase = (size_t)bb * SEQ;
        const int nIter = diag ? 4 : 6;

        #pragma unroll
        for (int iter = 0; iter < 6; ++iter) {
            if (iter >= nIter) break;
            const int row192 = iter * 32 + rsub;       // 0..191
            const bool isA   = (row192 < 128);
            const int  row   = isA ? row192 : (row192 - 128);
            const int  pos   = isA ? (mT * TILE + row192)
                                   : (ncol0 + row192 - 128);

            const uint32_t dst = smem + (isA ? OFF_A : OFF_B)
                               + (uint32_t)row * ROW_BYTES + (uint32_t)chunk * 16;
            cp_async16(dst, g_emb + (ebase + pos) * 64 + chunk * 8);
        }
        asm volatile("cp.async.commit_group;" ::: "memory");
        asm volatile("cp.async.wait_group 0;" ::: "memory");
    }
    __syncthreads();

    // ---- Warp tiling: 8 warps = 4 (M) x 2 (N); warp tile 32x32 ----
    const int wm = (wid >> 1) * 32;   // 0,32,64,96
    const int wn = (wid & 1) * 32;    // 0,32

    float acc[2][4][4];
    #pragma unroll
    for (int mi = 0; mi < 2; ++mi)
        #pragma unroll
        for (int nj = 0; nj < 4; ++nj)
            #pragma unroll
            for (int q = 0; q < 4; ++q) acc[mi][nj][q] = 0.f;

    const int a_row  = lane & 15;
    const int a_col  = (lane >> 4) * 8;
    const int b_row  = (lane & 7) + ((lane >> 4) * 8);
    const int b_col  = ((lane >> 3) & 1) * 8;

    const uint32_t a_base =
        smem + OFF_A + (uint32_t)(wm + a_row) * ROW_BYTES + (uint32_t)a_col * 2;
    const uint32_t b_tile = diag ? (smem + OFF_A + (uint32_t)(half * 64) * ROW_BYTES)
                                 : (smem + OFF_B);
    const uint32_t b_base =
        b_tile + (uint32_t)(wn + b_row) * ROW_BYTES + (uint32_t)b_col * 2;

    #pragma unroll
    for (int k = 0; k < 4; ++k) {           // k16 steps over K=64
        const uint32_t koff = (uint32_t)(k * 16) * 2;

        uint32_t bf[2][4];
        #pragma unroll
        for (int bj = 0; bj < 2; ++bj)
            ldsm4(bf[bj], b_base + koff + (uint32_t)(bj * 16) * ROW_BYTES);

        #pragma unroll
        for (int mi = 0; mi < 2; ++mi) {
            uint32_t af[4];
            ldsm4(af, a_base + koff + (uint32_t)(mi * 16) * ROW_BYTES);

            #pragma unroll
            for (int nj = 0; nj < 4; ++nj) {
                const uint32_t* bp = &bf[nj >> 1][(nj & 1) * 2];
                mma16816(acc[mi][nj], af, bp[0], bp[1]);
            }
        }
    }

    const int g = lane >> 2;     // row within 8
    const int t = lane & 3;      // col pair
    const bool oddl = (t & 1);

    // ---- Direct tile store FIRST: shfl-merge lane pairs into float4 STG.128.
    // (No epilogue scale: operands carry sqrt(1/8) each.)
    {
        float* obase = out + ((size_t)bb * SEQ + (size_t)(mT * TILE + wm + g)) * SEQ
                           + (size_t)(ncol0 + wn + 4 * (t >> 1));
        #pragma unroll
        for (int mi = 0; mi < 2; ++mi) {
            #pragma unroll
            for (int h = 0; h < 2; ++h) {
                float2 vv[4];
                #pragma unroll
                for (int nj = 0; nj < 4; ++nj) {
                    vv[nj].x = acc[mi][nj][2 * h + 0];
                    vv[nj].y = acc[mi][nj][2 * h + 1];
                }
                float2 s0 = oddl ? vv[0] : vv[2];
                float2 s1 = oddl ? vv[1] : vv[3];
                float2 r0, r1;
                r0.x = __shfl_xor_sync(0xFFFFFFFFu, s0.x, 1);
                r0.y = __shfl_xor_sync(0xFFFFFFFFu, s0.y, 1);
                r1.x = __shfl_xor_sync(0xFFFFFFFFu, s1.x, 1);
                r1.y = __shfl_xor_sync(0xFFFFFFFFu, s1.y, 1);

                float4 o0, o1;
                int njA, njB;
                if (!oddl) {
                    o0 = make_float4(vv[0].x, vv[0].y, r0.x, r0.y); njA = 0;
                    o1 = make_float4(vv[1].x, vv[1].y, r1.x, r1.y); njB = 1;
                } else {
                    o0 = make_float4(r0.x, r0.y, vv[2].x, vv[2].y); njA = 2;
                    o1 = make_float4(r1.x, r1.y, vv[3].x, vv[3].y); njB = 3;
                }
                float* rowp = obase + (size_t)(mi * 16 + 8 * h) * SEQ;
                __stcs(reinterpret_cast<float4*>(rowp + njA * 8), o0);
                __stcs(reinterpret_cast<float4*>(rowp + njB * 8), o1);
            }
        }
    }

    // ---- Off-diagonal: transpose-stage (reuses gather smem) then drain mirror
    if (!diag) {
        __syncthreads();   // all ldsm reads of gather smem complete
        // smem_t[c][r]: bank = (4c + r) mod 32 = 8t + g + const -> conflict-free
        #pragma unroll
        for (int mi = 0; mi < 2; ++mi) {
            #pragma unroll
            for (int nj = 0; nj < 4; ++nj) {
                #pragma unroll
                for (int h = 0; h < 2; ++h) {
                    const int row = wm + mi * 16 + 8 * h + g;
                    const int c0  = wn + nj * 8 + 2 * t;
                    smem_f[(c0 + 0) * LDT + row] = acc[mi][nj][2 * h + 0];
                    smem_f[(c0 + 1) * LDT + row] = acc[mi][nj][2 * h + 1];
                }
            }
        }
        __syncthreads();
        // mirror: out[b, ncol0+c, mT*128+r], coalesced float4 rows
        float* obase = out + ((size_t)bb * SEQ + (size_t)ncol0) * SEQ
                           + (size_t)(mT * TILE);
        #pragma unroll
        for (int i = 0; i < 8; ++i) {
            const int id = i * 256 + tid;
            const int r  = id >> 5;          // 0..63: row of mirrored tile
            const int c4 = id & 31;          // float4 index within row
            const float4 v = *reinterpret_cast<const float4*>(smem_f + r * LDT + c4 * 4);
            __stcs(reinterpret_cast<float4*>(obase + (size_t)r * SEQ + c4 * 4), v);
        }
    }
}

extern "C" void kernel_launch(void* const* d_in, const int* in_sizes, int n_in,
                              void* d_out, int out_size)
{
    const int*   seq    = (const int*)d_in[0];    // [16, 2048] int32
    const float* weight = (const float*)d_in[1];  // [32000, 64] fp32
    float*       out    = (float*)d_out;          // [16, 2048, 2048] fp32

    (void)in_sizes; (void)n_in; (void)out_size;

    cudaFuncSetAttribute(synergy_kernel,
                         cudaFuncAttributeMaxDynamicSharedMemorySize, SMEM_BYTES);

    // Kernel 1: materialize pre-scaled fp16 embedding table
    build_emb_kernel<<<(BATCH * SEQ * 16) / 256 / 4, 256>>>(seq, weight);

    // Kernel 2: symmetric GEMM, heavy (off-diag) CTAs first
    dim3 grid(NPAIRS, 2, BATCH);   // (136 pairs, 2 halves, 16 batches)
    synergy_kernel<<<grid, 256, SMEM_BYTES>>>(out);
}